// round 1
// baseline (speedup 1.0000x reference)
#include <cuda_runtime.h>

// SoftDTW forward, B=128, N=M=512, gamma=1.
// Transform: S = exp(-R)  =>  S[i][j] = exp(-D[i][j]) * (S[i-1][j-1] + S[i-1][j] + S[i][j-1])
// Final: R = -(log S[N-1][M-1] + accumulated rescale logs).
// One CTA per batch; thread j owns column j; anti-diagonal wavefront, one barrier per step.
// D staged per 32-diagonal chunk into shared as exp(-D), coalesced, pitch-33 (bank-conflict-free).

namespace {
constexpr int BATCH  = 128;
constexpr int NROWS  = 512;
constexpr int MCOLS  = 512;
constexpr int NWARP  = 16;
constexpr int NC     = 32;   // diagonal steps per chunk
constexpr int NCHUNK = 32;   // 32*32 = 1024 >= N+M-1 = 1023 steps
constexpr int PITCH  = 33;   // 33 mod 32 == 1 -> conflict-free strided LDS
constexpr int SMEM_BYTES = NROWS * PITCH * (int)sizeof(float);  // 67584
}

__global__ __launch_bounds__(512, 1)
void softdtw_fwd(const float* __restrict__ D, float* __restrict__ out) {
    extern __shared__ float sm[];                  // [NROWS][PITCH] staged exp(-D)
    __shared__ float bnd1[2][NWARP];               // lane-31 v1, double-buffered by diag parity
    __shared__ float bnd2[2][NWARP];               // lane-31 v2
    __shared__ float red[NWARP];                   // rescale max reduction

    const int b    = blockIdx.x;
    const int tid  = threadIdx.x;
    const int w    = tid >> 5;
    const int lane = tid & 31;
    const int j    = tid;                          // column owned by this thread
    const float* __restrict__ Db = D + (size_t)b * NROWS * MCOLS;

    // v1 = S[i-1][j] (my value 1 step ago), v2 = my value 2 steps ago.
    // Inactive (not-yet-started) threads hold 0 == virtual boundary S[-1][j].
    float v1 = 0.f, v2 = 0.f, acc = 0.f;

    for (int chunk = 0; chunk < NCHUNK; ++chunk) {
        const int d0 = chunk * NC;

        __syncthreads();  // previous chunk's compute done before sm overwrite
        {
            // Stage exp(-D) for diagonals [d0, d0+NC): row i needs cols [d0-i, d0-i+31].
            // Warp w handles rows [32w, 32w+32); lane l -> t=l, col jj = d0 - i + l.
            const int ibase = w << 5;
            #pragma unroll 8
            for (int r = 0; r < 32; ++r) {
                const int i  = ibase + r;
                const int jj = d0 - i + lane;
                if (jj >= 0 && jj < MCOLS)
                    sm[i * PITCH + lane] = __expf(-Db[i * MCOLS + jj]);
            }
        }
        __syncthreads();

        // Inner wavefront: cell (i = d - j, j) read at sm[(d-j)*PITCH + t]; per-step stride PITCH+1.
        int idx = (d0 - j) * PITCH;
        #pragma unroll
        for (int t = 0; t < NC; ++t) {
            const int d   = d0 + t;
            const int par = d & 1;
            if (lane == 31) { bnd1[par][w] = v1; bnd2[par][w] = v2; }
            __syncthreads();
            float n1 = __shfl_up_sync(0xffffffffu, v1, 1);  // S[i][j-1]   (left)
            float n2 = __shfl_up_sync(0xffffffffu, v2, 1);  // S[i-1][j-1] (diag)
            if (lane == 0) {
                if (w > 0) { n1 = bnd1[par][w - 1]; n2 = bnd2[par][w - 1]; }
                else       { n1 = 0.f; n2 = (d == 0) ? 1.f : 0.f; }  // virtual corner S[-1][-1]=1
            }
            const int i = d - j;
            if (i >= 0 && i < NROWS) {
                const float v = sm[idx] * ((n2 + v1) + n1);
                v2 = v1;
                v1 = v;
            }
            idx += PITCH + 1;
        }

        // Block-wide rescale: keep S in fp32 range (growth <= 3^32 per chunk).
        float m = fmaxf(v1, v2);
        #pragma unroll
        for (int o = 16; o > 0; o >>= 1)
            m = fmaxf(m, __shfl_xor_sync(0xffffffffu, m, o));
        if (lane == 0) red[w] = m;
        __syncthreads();
        float mx = red[0];
        #pragma unroll
        for (int k = 1; k < NWARP; ++k) mx = fmaxf(mx, red[k]);
        const float inv = 1.0f / mx;
        v1 *= inv;
        v2 *= inv;
        acc += logf(mx);
    }

    // Cell (N-1, M-1) was computed by thread j = M-1 at d = 1022 -> sits in its v1.
    if (j == MCOLS - 1) out[b] = -(logf(v1) + acc);
}

extern "C" void kernel_launch(void* const* d_in, const int* in_sizes, int n_in,
                              void* d_out, int out_size) {
    (void)in_sizes; (void)n_in; (void)out_size;
    const float* D = (const float*)d_in[0];
    float* out     = (float*)d_out;
    cudaFuncSetAttribute(softdtw_fwd, cudaFuncAttributeMaxDynamicSharedMemorySize, SMEM_BYTES);
    softdtw_fwd<<<BATCH, 512, SMEM_BYTES>>>(D, out);
}

// round 2
// speedup vs baseline: 1.0023x; 1.0023x over previous
#include <cuda_runtime.h>

// SoftDTW forward, B=128, N=M=512, gamma=1.
// Transform: S = exp(-R)  =>  S[i][j] = exp(-D[i][j]) * (S[i-1][j-1] + S[i-1][j] + S[i][j-1])
// Final: R = -(log S[N-1][M-1] + accumulated rescale logs).
// One CTA per batch; thread j owns column j; anti-diagonal wavefront, one barrier per step.
// D staged per 32-diagonal chunk into shared as exp(-D), coalesced, pitch-33 (bank-conflict-free).

namespace {
constexpr int BATCH  = 128;
constexpr int NROWS  = 512;
constexpr int MCOLS  = 512;
constexpr int NWARP  = 16;
constexpr int NC     = 32;   // diagonal steps per chunk
constexpr int NCHUNK = 32;   // 32*32 = 1024 >= N+M-1 = 1023 steps
constexpr int PITCH  = 33;   // 33 mod 32 == 1 -> conflict-free strided LDS
constexpr int SMEM_BYTES = NROWS * PITCH * (int)sizeof(float);  // 67584
}

__global__ __launch_bounds__(512, 1)
void softdtw_fwd(const float* __restrict__ D, float* __restrict__ out) {
    extern __shared__ float sm[];                  // [NROWS][PITCH] staged exp(-D)
    __shared__ float bnd1[2][NWARP];               // lane-31 v1, double-buffered by diag parity
    __shared__ float bnd2[2][NWARP];               // lane-31 v2
    __shared__ float red[NWARP];                   // rescale max reduction

    const int b    = blockIdx.x;
    const int tid  = threadIdx.x;
    const int w    = tid >> 5;
    const int lane = tid & 31;
    const int j    = tid;                          // column owned by this thread
    const float* __restrict__ Db = D + (size_t)b * NROWS * MCOLS;

    // v1 = S[i-1][j] (my value 1 step ago), v2 = my value 2 steps ago.
    // Inactive (not-yet-started) threads hold 0 == virtual boundary S[-1][j].
    float v1 = 0.f, v2 = 0.f, acc = 0.f;

    for (int chunk = 0; chunk < NCHUNK; ++chunk) {
        const int d0 = chunk * NC;

        __syncthreads();  // previous chunk's compute done before sm overwrite
        {
            // Stage exp(-D) for diagonals [d0, d0+NC): row i needs cols [d0-i, d0-i+31].
            // Warp w handles rows [32w, 32w+32); lane l -> t=l, col jj = d0 - i + l.
            const int ibase = w << 5;
            #pragma unroll 8
            for (int r = 0; r < 32; ++r) {
                const int i  = ibase + r;
                const int jj = d0 - i + lane;
                if (jj >= 0 && jj < MCOLS)
                    sm[i * PITCH + lane] = __expf(-Db[i * MCOLS + jj]);
            }
        }
        __syncthreads();

        // Inner wavefront: cell (i = d - j, j) read at sm[(d-j)*PITCH + t]; per-step stride PITCH+1.
        int idx = (d0 - j) * PITCH;
        #pragma unroll
        for (int t = 0; t < NC; ++t) {
            const int d   = d0 + t;
            const int par = d & 1;
            if (lane == 31) { bnd1[par][w] = v1; bnd2[par][w] = v2; }
            __syncthreads();
            float n1 = __shfl_up_sync(0xffffffffu, v1, 1);  // S[i][j-1]   (left)
            float n2 = __shfl_up_sync(0xffffffffu, v2, 1);  // S[i-1][j-1] (diag)
            if (lane == 0) {
                if (w > 0) { n1 = bnd1[par][w - 1]; n2 = bnd2[par][w - 1]; }
                else       { n1 = 0.f; n2 = (d == 0) ? 1.f : 0.f; }  // virtual corner S[-1][-1]=1
            }
            const int i = d - j;
            if (i >= 0 && i < NROWS) {
                const float v = sm[idx] * ((n2 + v1) + n1);
                v2 = v1;
                v1 = v;
            }
            idx += PITCH + 1;
        }

        // Block-wide rescale: keep S in fp32 range (growth <= 3^32 per chunk).
        float m = fmaxf(v1, v2);
        #pragma unroll
        for (int o = 16; o > 0; o >>= 1)
            m = fmaxf(m, __shfl_xor_sync(0xffffffffu, m, o));
        if (lane == 0) red[w] = m;
        __syncthreads();
        float mx = red[0];
        #pragma unroll
        for (int k = 1; k < NWARP; ++k) mx = fmaxf(mx, red[k]);
        const float inv = 1.0f / mx;
        v1 *= inv;
        v2 *= inv;
        acc += logf(mx);
    }

    // Cell (N-1, M-1) was computed by thread j = M-1 at d = 1022 -> sits in its v1.
    if (j == MCOLS - 1) out[b] = -(logf(v1) + acc);
}

extern "C" void kernel_launch(void* const* d_in, const int* in_sizes, int n_in,
                              void* d_out, int out_size) {
    (void)in_sizes; (void)n_in; (void)out_size;
    const float* D = (const float*)d_in[0];
    float* out     = (float*)d_out;
    cudaFuncSetAttribute(softdtw_fwd, cudaFuncAttributeMaxDynamicSharedMemorySize, SMEM_BYTES);
    softdtw_fwd<<<BATCH, 512, SMEM_BYTES>>>(D, out);
}

// round 3
// speedup vs baseline: 4.6172x; 4.6067x over previous
#include <cuda_runtime.h>

// SoftDTW forward, B=128, N=M=512, gamma=1.
// S = exp(-R):  S[i][j] = exp(-D[i][j]) * (S[i-1][j-1] + S[i-1][j] + S[i][j-1])
// Final: R = -(ln S + Es*ln2), with warp-uniform power-of-2 rescaling (Es ledger).
//
// One CTA per batch, 4 warps:
//   warps 0-2: producers — stream D, compute exp(-D), stage into a 44-slot smem ring,
//              diagonal placement: chunk (row r, consumer-lane l) -> slot (r+l) % 44.
//   warp 3:    consumer — wavefront DP, lane l owns cols [16l,16l+16); at step s lane l
//              processes row i = s-l. All lanes read ONE slot (s % 44) per step.
//              Neighbor passing: one shfl_up per step. No barriers in the step loop.
// Phases of 6 steps/rows; one __syncthreads per phase orders producer->consumer.

namespace {
constexpr int BATCH   = 128;
constexpr int NR      = 512;
constexpr int MC      = 512;
constexpr int KP      = 6;                      // steps/rows per phase
constexpr int RS      = 44;                     // ring slots
constexpr int LSTRIDE = 36;                     // words per lane chunk (144B): conflict-free, 16B-aligned
constexpr int SLOTW   = 32 * LSTRIDE;           // 1152 words per slot
constexpr int SMEM_BYTES = RS * SLOTW * 4;      // 202752 B
constexpr int STEPS   = NR + 31;                // 543
constexpr int NPHASE  = (STEPS + KP - 1) / KP;  // 91
constexpr unsigned FULL = 0xffffffffu;
}

__device__ __forceinline__ float4 exp4neg(float4 v) {
    float4 r;
    r.x = __expf(-v.x); r.y = __expf(-v.y);
    r.z = __expf(-v.z); r.w = __expf(-v.w);
    return r;
}

__global__ __launch_bounds__(128, 1)
void softdtw_fwd(const float* __restrict__ D, float* __restrict__ out) {
    extern __shared__ float sm[];
    const int b   = blockIdx.x;
    const int tid = threadIdx.x;
    const int w   = tid >> 5;
    const int l   = tid & 31;
    const float* __restrict__ G = D + (size_t)b * NR * MC + l * 16;

    if (w < 3) {
        // ---------------- producers (warps 0,1,2) ----------------
        float* lane_base = sm + l * LSTRIDE;

        auto load_row = [&](int r, float4 a[4]) {
            const float4* src = (const float4*)(G + (size_t)r * MC);
            a[0] = src[0]; a[1] = src[1]; a[2] = src[2]; a[3] = src[3];
        };
        auto store_row = [&](int r, const float4 a[4]) {
            float4* dst = (float4*)(lane_base + ((r + l) % RS) * SLOTW);
            dst[0] = exp4neg(a[0]); dst[1] = exp4neg(a[1]);
            dst[2] = exp4neg(a[2]); dst[3] = exp4neg(a[3]);
        };

        float4 A[4], Bv[4];
        // block 0 (rows 0..5) written directly before the loop
        {
            float4 t0[4];
            int r0 = 2 * w;
            load_row(r0, t0);     store_row(r0, t0);
            load_row(r0 + 1, t0); store_row(r0 + 1, t0);
        }
        // prefetch block 1
        { int r0 = KP + 2 * w; load_row(r0, A); load_row(r0 + 1, Bv); }

        for (int t = 0; t < NPHASE; ++t) {
            __syncthreads();
            // write block t+1 (prefetched last phase)
            const int r0 = KP * (t + 1) + 2 * w;   // r0 even -> r0+1 valid iff r0 valid
            if (r0 < NR) { store_row(r0, A); store_row(r0 + 1, Bv); }
            // prefetch block t+2
            const int r2 = r0 + KP;
            if (r2 < NR) { load_row(r2, A); load_row(r2 + 1, Bv); }
        }
    } else {
        // ---------------- consumer (warp 3) ----------------
        float h[16];
        #pragma unroll
        for (int j = 0; j < 16; ++j) h[j] = 0.f;
        float xd = (l == 0) ? 1.f : 0.f;   // diag carry; corner S[-1][-1] = 1
        int   Es = 0;
        int   slot = 0;
        const float* lane_base = sm + l * LSTRIDE;

        for (int t = 0; t < NPHASE; ++t) {
            __syncthreads();
            #pragma unroll
            for (int q = 0; q < KP; ++q) {
                const int s = t * KP + q;
                if (s < STEPS) {
                    const float4* eb = (const float4*)(lane_base + slot * SLOTW);
                    const float4 E0 = eb[0], E1 = eb[1], E2 = eb[2], E3 = eb[3];
                    float e[16] = { E0.x, E0.y, E0.z, E0.w,
                                    E1.x, E1.y, E1.z, E1.w,
                                    E2.x, E2.y, E2.z, E2.w,
                                    E3.x, E3.y, E3.z, E3.w };

                    // left neighbor: lane l-1's col-(16l-1) value at row i (its step s-1)
                    const float x  = __shfl_up_sync(FULL, h[15], 1);
                    const float xl = (l == 0) ? 0.f : x;
                    const bool  act = (unsigned)(s - l) < (unsigned)NR;

                    float p[16];
                    p[0] = e[0] * (xd + h[0]);
                    #pragma unroll
                    for (int j = 1; j < 16; ++j) p[j] = e[j] * (h[j - 1] + h[j]);

                    float c = xl;
                    #pragma unroll
                    for (int j = 0; j < 16; ++j) {
                        c = fmaf(e[j], c, p[j]);
                        h[j] = act ? c : h[j];     // freeze h outside [start,end]
                    }
                    xd = xl;                        // this step's left = next step's diag
                    slot = (slot + 1 == RS) ? 0 : slot + 1;

                    // warp-uniform power-of-2 rescale every 32 steps
                    if ((s & 31) == 31) {
                        float m = h[0];
                        #pragma unroll
                        for (int j = 1; j < 16; ++j) m = fmaxf(m, h[j]);
                        #pragma unroll
                        for (int o = 16; o; o >>= 1)
                            m = fmaxf(m, __shfl_xor_sync(FULL, m, o));
                        if (m > 0.f) {
                            const int   k = (__float_as_int(m) >> 23) - 127;
                            const float f = __int_as_float((127 - k) << 23);
                            #pragma unroll
                            for (int j = 0; j < 16; ++j) h[j] *= f;
                            xd *= f;
                            Es += k;
                        }
                    }
                }
            }
        }
        // cell (511,511) computed by lane 31 at step 542 -> h[15]
        if (l == 31)
            out[b] = -(logf(h[15]) + (float)Es * 0.69314718055994531f);
    }
}

extern "C" void kernel_launch(void* const* d_in, const int* in_sizes, int n_in,
                              void* d_out, int out_size) {
    (void)in_sizes; (void)n_in; (void)out_size;
    const float* D = (const float*)d_in[0];
    float* o       = (float*)d_out;
    cudaFuncSetAttribute(softdtw_fwd, cudaFuncAttributeMaxDynamicSharedMemorySize, SMEM_BYTES);
    softdtw_fwd<<<BATCH, 128, SMEM_BYTES>>>(D, o);
}